// round 12
// baseline (speedup 1.0000x reference)
#include <cuda_runtime.h>
#include <cuda_fp16.h>
#include <math.h>
#include <stdint.h>

// Problem constants
constexpr int B_ = 4, S_ = 4096, D_ = 64;
constexpr int MT = 64;            // q rows per tile
constexpr int NT = 128;           // keys per k-tile
constexpr float QSCALE = 0.18033688011112042f;  // 0.125 * log2(e), folded into Q

// ---- global scratch (allocation-free rule) ----
__device__ __align__(16) __half g_Qh[B_*S_*D_];
__device__ __align__(16) __half g_Kh[B_*S_*D_];   // zeroed on padded keys
__device__ __align__(16) __half g_Vh[B_*S_*D_];   // zeroed on padded keys
__device__ __align__(16) __half g_pad1h[B_*S_];   // 1.0 keep / 0.0 masked
__device__ float g_part[256][D_];                 // V_p column sums per proj block

// ---- f32x2 helpers (proj kernel) ----
using u64_t = unsigned long long;
__device__ __forceinline__ u64_t fma2(u64_t a, u64_t b, u64_t c) {
    u64_t d; asm("fma.rn.f32x2 %0, %1, %2, %3;" : "=l"(d) : "l"(a), "l"(b), "l"(c)); return d;
}
__device__ __forceinline__ float2 unpack2(u64_t v) {
    float2 r; asm("mov.b64 {%0, %1}, %2;" : "=f"(r.x), "=f"(r.y) : "l"(v)); return r;
}

__device__ __forceinline__ uint32_t smem_u32(const void* p) {
    uint32_t a;
    asm("{ .reg .u64 t; cvta.to.shared.u64 t, %1; cvt.u32.u64 %0, t; }" : "=r"(a) : "l"(p));
    return a;
}

// ---- mma.sync / ldmatrix / misc PTX ----
__device__ __forceinline__ void ldm_x4(uint32_t* r, uint32_t a) {
    asm volatile("ldmatrix.sync.aligned.m8n8.x4.shared.b16 {%0,%1,%2,%3}, [%4];"
                 : "=r"(r[0]), "=r"(r[1]), "=r"(r[2]), "=r"(r[3]) : "r"(a));
}
__device__ __forceinline__ void ldm_x4_t(uint32_t* r, uint32_t a) {
    asm volatile("ldmatrix.sync.aligned.m8n8.x4.trans.shared.b16 {%0,%1,%2,%3}, [%4];"
                 : "=r"(r[0]), "=r"(r[1]), "=r"(r[2]), "=r"(r[3]) : "r"(a));
}
__device__ __forceinline__ void mma_f16(float* c, const uint32_t* a, const uint32_t* b) {
    asm volatile("mma.sync.aligned.m16n8k16.row.col.f32.f16.f16.f32 "
                 "{%0,%1,%2,%3}, {%4,%5,%6,%7}, {%8,%9}, {%0,%1,%2,%3};"
                 : "+f"(c[0]), "+f"(c[1]), "+f"(c[2]), "+f"(c[3])
                 : "r"(a[0]), "r"(a[1]), "r"(a[2]), "r"(a[3]), "r"(b[0]), "r"(b[1]));
}
__device__ __forceinline__ float ex2(float x) {
    float y; asm("ex2.approx.f32 %0, %1;" : "=f"(y) : "f"(x)); return y;
}
// pack two fp32 -> fp16x2; second arg lands in the LOW half
__device__ __forceinline__ uint32_t cvt_f16x2(float hi, float lo) {
    uint32_t r; asm("cvt.rn.f16x2.f32 %0, %1, %2;" : "=r"(r) : "f"(hi), "f"(lo)); return r;
}
__device__ __forceinline__ uint32_t lds32(uint32_t a) {
    uint32_t v; asm volatile("ld.shared.b32 %0, [%1];" : "=r"(v) : "r"(a)); return v;
}
__device__ __forceinline__ void cpa16(uint32_t dst, const void* src) {
    asm volatile("cp.async.cg.shared.global [%0], [%1], 16;" :: "r"(dst), "l"(src));
}
#define CP_COMMIT() asm volatile("cp.async.commit_group;" ::: "memory")
#define CP_WAIT0()  asm volatile("cp.async.wait_group 0;" ::: "memory")

// ---------------------------------------------------------------------------
// Kernel 1: fused pad canonicalization + QKV projection + popularity
// modulation -> single fp16 (padded K/V rows zeroed at the fp16 store),
// plus per-block UN-zeroed V_p column sums (for the meanV fallback).
// 256 blocks x 256 threads; 4 threads per row (16 output features each).
// ---------------------------------------------------------------------------
__global__ __launch_bounds__(256) void proj_kernel(
    const float* __restrict__ E,  const float* __restrict__ PK, const float* __restrict__ PV,
    const float* __restrict__ Wq, const float* __restrict__ bq,
    const float* __restrict__ Wk, const float* __restrict__ bk,
    const float* __restrict__ Wv, const float* __restrict__ bv,
    const void* __restrict__ pad)
{
    __shared__ float Wsm[3][D_ * D_];     // 48 KB; Wsm[0] reused as reduction scratch
    __shared__ float bsm[3][64];
    __shared__ float keepf[64];
    __shared__ int f[2];
    const int t = threadIdx.x;
    const int rloc = t & 63, cq = t >> 6;     // row in block, column quarter
    const int cbase = cq * 16;
    const size_t g = (size_t)blockIdx.x * 64 + rloc;

    if (t < 2) f[t] = 0;

    // ---- stage W matrices + biases ----
    {
        const float* Ws[3] = {Wq, Wk, Wv};
        #pragma unroll
        for (int m = 0; m < 3; m++) {
            float4* dst = reinterpret_cast<float4*>(Wsm[m]);
            const float4* src = reinterpret_cast<const float4*>(Ws[m]);
            #pragma unroll
            for (int i = 0; i < 4; i++) dst[t + i * 256] = src[t + i * 256];
        }
        if (t < 64) { bsm[0][t] = bq[t]; bsm[1][t] = bk[t]; bsm[2][t] = bv[t]; }
    }

    // ---- pad dtype detection (independent per block; 16KB scan = min buffer) ----
    {
        const uint4* p4 = reinterpret_cast<const uint4*>(pad);   // 1024 x 16B
        uint32_t ge2 = 0, odd = 0;
        #pragma unroll
        for (int i = t; i < 1024; i += 256) {
            uint4 v = p4[i];
            uint32_t o = v.x | v.y | v.z | v.w;
            ge2 |= o & 0xFEFEFEFEu;     // any byte >= 2 anywhere -> float32
            odd |= o & 0xFFFFFF00u;     // any nonzero byte at idx%4 != 0 -> uint8
        }
        if (ge2) atomicOr(&f[0], 1);
        if (odd) atomicOr(&f[1], 1);
    }
    __syncthreads();

    // ---- canonical half mask + keep flags for this block's 64 rows ----
    if (t < 64) {
        const int kind = f[0] ? 2 : (f[1] ? 0 : 1);   // 0=u8, 1=i32, 2=f32
        const int i = blockIdx.x * 64 + t;
        bool m;
        if (kind == 0)      m = ((const unsigned char*)pad)[i] != 0;
        else if (kind == 1) m = ((const int*)pad)[i] != 0;
        else                m = ((const float*)pad)[i] != 0.f;
        const float k = m ? 0.f : 1.f;
        keepf[t] = k;
        g_pad1h[i] = __float2half(k);
    }
    __syncthreads();

    u64_t e2[32];
    {
        const ulonglong2* er = reinterpret_cast<const ulonglong2*>(E + g * D_);
        #pragma unroll
        for (int i = 0; i < 16; i++) { ulonglong2 v = er[i]; e2[2*i] = v.x; e2[2*i+1] = v.y; }
    }

    const float keep = keepf[rloc];
    __half* oh3[3] = {g_Qh, g_Kh, g_Vh};
    float outv[16];

    #pragma unroll
    for (int m = 0; m < 3; m++) {
        #pragma unroll 4
        for (int c = 0; c < 16; c++) {
            const ulonglong2* wr = reinterpret_cast<const ulonglong2*>(Wsm[m] + (cbase + c) * D_);
            u64_t a0 = 0ull, a1 = 0ull;
            #pragma unroll
            for (int d8 = 0; d8 < 16; d8++) {
                ulonglong2 w = wr[d8];
                a0 = fma2(e2[2*d8],   w.x, a0);
                a1 = fma2(e2[2*d8+1], w.y, a1);
            }
            float2 p0 = unpack2(a0), p1 = unpack2(a1);
            outv[c] = bsm[m][cbase + c] + ((p0.x + p0.y) + (p1.x + p1.y));
        }
        if (m == 0) {
            #pragma unroll
            for (int c = 0; c < 16; c++) outv[c] *= QSCALE;
        } else {
            const float* mod = (m == 1 ? PK : PV) + g * D_ + cbase;
            #pragma unroll
            for (int c = 0; c < 16; c++) outv[c] *= mod[c];
        }
        // fp16 store; K/V rows of padded keys are zeroed HERE (outv stays
        // unzeroed so the meanV partial below uses the true V_p)
        const float zf = (m == 0) ? 1.f : keep;
        unsigned short hb[16];
        #pragma unroll
        for (int c = 0; c < 16; c++)
            hb[c] = __half_as_ushort(__float2half_rn(outv[c] * zf));
        uint4* oh = reinterpret_cast<uint4*>(oh3[m] + g * D_ + cbase);
        const uint4* sh = reinterpret_cast<const uint4*>(hb);
        #pragma unroll
        for (int i = 0; i < 2; i++) oh[i] = sh[i];
    }

    // ---- meanV partial: outv holds this thread's quarter-row of fp32 V_p ----
    __syncthreads();                       // everyone done reading Wsm
    float* red = Wsm[0];                   // 64 x 64 f32 = 16 KB
    #pragma unroll
    for (int i = 0; i < 4; i++)
        reinterpret_cast<float4*>(red + rloc * 64 + cbase)[i] =
            make_float4(outv[4*i], outv[4*i+1], outv[4*i+2], outv[4*i+3]);
    __syncthreads();
    if (t < 64) {
        float a = 0.f;
        #pragma unroll 8
        for (int r = 0; r < 64; r++) a += red[r * 64 + t];
        g_part[blockIdx.x][t] = a;
    }
}

// ---------------------------------------------------------------------------
// Kernel 2: single-fp16 mma.sync flash attention, cp.async double-buffered.
// CTA = 256 threads = 4 row-warps x 2 key-halves, ONE 64-row q-tile per CTA.
// Grid = 256 CTAs, all co-resident at occupancy 2 (regs capped at 128 by
// chunked score computation). bid->(b,qt) mapping exploits the bid%148 SM
// placement period: co-resident pairs (i, i+148) sum to exactly 28 k-tiles
// (qt paired with 53-qt) and the 40 heaviest tiles get the 40 singleton SMs.
// Padding folded into the GEMMs (zeroed K/V + ones-mask MMA for l).
// ---------------------------------------------------------------------------
constexpr int SM_QH   = 0;                      // 64 x 128B
constexpr int SM_KV   = 8192;                   // 2 stages x (K 16KB + V 16KB)
constexpr int STG_SZ  = 32768;
constexpr int OFF_K   = 0, OFF_V = 16384;
constexpr int SM_PADB = SM_KV + 2 * STG_SZ;     // 73728, 2 x 256B (half mask)
constexpr int SM_LSM  = SM_PADB + 512;          // 74240, 2 x 64 f32
constexpr int SM_MNV  = SM_LSM + 512;           // 74752, 64 f32
constexpr int SM_MRG  = SM_KV;                  // merge overlays stage 0 (drained)
constexpr int SM_TOTAL = SM_MNV + 256;          // 75008

__global__ __launch_bounds__(256, 2) void attn_mma_kernel(float* __restrict__ out)
{
    extern __shared__ char sm[];
    const uint32_t smb = smem_u32(sm);
    const int tid = threadIdx.x, wid = tid >> 5, lane = tid & 31;
    const int wr = wid & 3, wc = wid >> 2;        // row-warp, key-half
    const int g8 = lane >> 3, l8 = lane & 7, l4 = lane >> 2, lq = lane & 3;
    float* lsm  = reinterpret_cast<float*>(sm + SM_LSM);
    float* mnv  = reinterpret_cast<float*>(sm + SM_MNV);
    float* mrg  = reinterpret_cast<float*>(sm + SM_MRG);

    // ---- bid -> (b, qt): balance work across same-SM CTA pairs ----
    const int bid = blockIdx.x;
    int b, qt;
    if (bid >= 148)      { const int i = bid - 148; b = i / 27; qt = i % 27; }
    else if (bid >= 108) { const int i = bid - 108; qt = 54 + (i >> 2); b = i & 3; }
    else                 { b = bid / 27; qt = 53 - (bid % 27); }

    const int qbase = qt * MT;
    const int nkt = (qt >> 1) + 1;

    // ---- meanV for this batch (sum of 64 proj-block partials) ----
    if (tid < 64) {
        float a = 0.f;
        #pragma unroll 8
        for (int i = 0; i < 64; i++) a += g_part[b * 64 + i][tid];
        mnv[tid] = a * (1.0f / (float)S_);
    }

    // ---- prologue: async-copy Q + k-tile 0 into stage 0 ----
    {
        const uint4* qh4 = reinterpret_cast<const uint4*>(g_Qh + ((size_t)b * S_ + qbase) * D_);
        #pragma unroll
        for (int it = 0; it < 2; it++) {
            int i = tid + it * 256;            // 512 chunks
            int row = i >> 3, c = i & 7;
            uint32_t sw = row * 128 + (((uint32_t)(c ^ (row & 7))) << 4);
            cpa16(smb + SM_QH + sw, qh4 + i);
        }
        const __half* srcs[2] = {g_Kh + (size_t)b * S_ * D_, g_Vh + (size_t)b * S_ * D_};
        #pragma unroll
        for (int t2 = 0; t2 < 2; t2++) {
            #pragma unroll
            for (int it = 0; it < 4; it++) {
                int i = tid + it * 256;        // 1024 chunks per tile
                int row = i >> 3, c = i & 7;
                uint32_t dst = smb + SM_KV + t2 * 16384 + row * 128 + (((uint32_t)(c ^ (row & 7))) << 4);
                cpa16(dst, reinterpret_cast<const uint4*>(srcs[t2]) + i);
            }
        }
        if (tid < 16)
            cpa16(smb + SM_PADB + tid * 16, (const char*)(g_pad1h + b * S_) + tid * 16);
        CP_COMMIT();
    }
    CP_WAIT0();
    __syncthreads();

    // ---- Q A-fragments, 4 d-chunks of 16 ----
    uint32_t qh[4][4];
    {
        const int row = wr * 16 + (g8 & 1) * 8 + l8;
        #pragma unroll
        for (int dc = 0; dc < 4; dc++) {
            const int c = 2 * dc + (g8 >> 1);
            ldm_x4(qh[dc], smb + SM_QH + row * 128 + (((uint32_t)(c ^ (row & 7))) << 4));
        }
    }

    float OC[8][4];
    #pragma unroll
    for (int i = 0; i < 8; i++)
        { OC[i][0] = 0.f; OC[i][1] = 0.f; OC[i][2] = 0.f; OC[i][3] = 0.f; }
    float LM[4] = {0.f, 0.f, 0.f, 0.f};   // l accumulator (MMA C-fragment)
    const int q0 = qbase + wr * 16 + l4, q1 = q0 + 8;
    const int kb0 = wc * 64;

    #pragma unroll 1
    for (int j = 0; j < nkt; j++) {
        const int st = j & 1;
        const uint32_t stb = smb + SM_KV + st * STG_SZ;
        const uint32_t padb = smb + SM_PADB + st * 256;
        const int kt = j * NT;

        // issue copy for tile j+1 into the other stage (overlaps compute)
        if (j + 1 < nkt) {
            const int ktn = (j + 1) * NT;
            const uint32_t nstb = smb + SM_KV + ((j + 1) & 1) * STG_SZ;
            const __half* srcs[2] = {g_Kh + ((size_t)b * S_ + ktn) * D_,
                                     g_Vh + ((size_t)b * S_ + ktn) * D_};
            #pragma unroll
            for (int t2 = 0; t2 < 2; t2++) {
                #pragma unroll
                for (int it = 0; it < 4; it++) {
                    int i = tid + it * 256;
                    int row = i >> 3, c = i & 7;
                    uint32_t dst = nstb + t2 * 16384 + row * 128 + (((uint32_t)(c ^ (row & 7))) << 4);
                    cpa16(dst, reinterpret_cast<const uint4*>(srcs[t2]) + i);
                }
            }
            if (tid < 16)
                cpa16(smb + SM_PADB + ((j + 1) & 1) * 256 + tid * 16,
                      (const char*)(g_pad1h + b * S_ + ktn) + tid * 16);
            CP_COMMIT();
        }

        // ---- S = Q K^T per 16-key chunk, ex2'd immediately (low reg peak) ----
        uint32_t Ph[4][4];
        const bool interior = (j < nkt - 1);
        const int krow0 = kb0 + (g8 >> 1) * 8 + l8;
        #pragma unroll
        for (int kp = 0; kp < 4; kp++) {
            float SC[2][4];
            #pragma unroll
            for (int h2 = 0; h2 < 2; h2++)
                { SC[h2][0] = 0.f; SC[h2][1] = 0.f; SC[h2][2] = 0.f; SC[h2][3] = 0.f; }
            const int row = krow0 + kp * 16;
            #pragma unroll
            for (int dc = 0; dc < 4; dc++) {
                const int c = 2 * dc + (g8 & 1);
                uint32_t bh[4];
                ldm_x4(bh, stb + OFF_K + row * 128 + (((uint32_t)(c ^ (row & 7))) << 4));
                mma_f16(SC[0], qh[dc], bh);
                mma_f16(SC[1], qh[dc], bh + 2);
            }
            if (interior) {
                #pragma unroll
                for (int h2 = 0; h2 < 2; h2++) {
                    const float p00 = ex2(SC[h2][0]);
                    const float p01 = ex2(SC[h2][1]);
                    const float p10 = ex2(SC[h2][2]);
                    const float p11 = ex2(SC[h2][3]);
                    Ph[kp][h2 * 2]     = cvt_f16x2(p01, p00);
                    Ph[kp][h2 * 2 + 1] = cvt_f16x2(p11, p10);
                }
            } else {
                #pragma unroll
                for (int h2 = 0; h2 < 2; h2++) {
                    const int key = kt + kb0 + (2 * kp + h2) * 8 + 2 * lq;
                    const float p00 = (key     <= q0) ? ex2(SC[h2][0]) : 0.f;
                    const float p01 = (key + 1 <= q0) ? ex2(SC[h2][1]) : 0.f;
                    const float p10 = (key     <= q1) ? ex2(SC[h2][2]) : 0.f;
                    const float p11 = (key + 1 <= q1) ? ex2(SC[h2][3]) : 0.f;
                    Ph[kp][h2 * 2]     = cvt_f16x2(p01, p00);
                    Ph[kp][h2 * 2 + 1] = cvt_f16x2(p11, p10);
                }
            }
        }

        // ---- l += P . mask (one n=8 MMA per 16-key chunk) ----
        {
            #pragma unroll
            for (int kc = 0; kc < 4; kc++) {
                const uint32_t a = padb + (uint32_t)(kb0 + kc * 16 + 2 * lq) * 2;
                uint32_t bm[2];
                bm[0] = lds32(a);
                bm[1] = lds32(a + 16);
                mma_f16(LM, Ph[kc], bm);
            }
        }

        // ---- O += P V (V via ldmatrix.trans) ----
        {
            const int vrow0 = kb0 + (g8 & 1) * 8 + l8;
            #pragma unroll
            for (int kc = 0; kc < 4; kc++) {
                #pragma unroll
                for (int ndp = 0; ndp < 4; ndp++) {
                    const int row = vrow0 + kc * 16;
                    const int c = 2 * ndp + (g8 >> 1);
                    uint32_t bh[4];
                    ldm_x4_t(bh, stb + OFF_V + row * 128 + (((uint32_t)(c ^ (row & 7))) << 4));
                    mma_f16(OC[2*ndp],   Ph[kc], bh);
                    mma_f16(OC[2*ndp+1], Ph[kc], bh + 2);
                }
            }
        }

        if (j + 1 < nkt) CP_WAIT0();
        __syncthreads();
    }

    // ---- merge the two key-halves (ADD; no rescaling needed) ----
    // LM cols identical across n (mask B same): LM[0]=l(q0), LM[2]=l(q1)
    if (lq == 0) {
        lsm[wc * 64 + wr * 16 + l4]     = LM[0];
        lsm[wc * 64 + wr * 16 + 8 + l4] = LM[2];
    }
    if (wc == 1) {
        const int r0 = wr * 16 + l4;
        #pragma unroll
        for (int nd = 0; nd < 8; nd++) {
            const int d0 = nd * 8 + 2 * lq;
            *reinterpret_cast<float2*>(&mrg[r0 * 64 + d0])       = make_float2(OC[nd][0], OC[nd][1]);
            *reinterpret_cast<float2*>(&mrg[(r0 + 8) * 64 + d0]) = make_float2(OC[nd][2], OC[nd][3]);
        }
    }
    __syncthreads();
    if (wc == 0) {
        const int r0 = wr * 16 + l4;
        const float lt0 = lsm[r0] + lsm[64 + r0];
        const float lt1 = lsm[r0 + 8] + lsm[64 + r0 + 8];
        const bool am0 = (lt0 == 0.f), am1 = (lt1 == 0.f);
        const float inv0 = am0 ? 0.f : 1.f / lt0;
        const float inv1 = am1 ? 0.f : 1.f / lt1;
        const int qr0 = qbase + r0, qr1 = qr0 + 8;
        #pragma unroll
        for (int nd = 0; nd < 8; nd++) {
            const int d0 = nd * 8 + 2 * lq;
            const float2 m0v = *reinterpret_cast<const float2*>(&mrg[r0 * 64 + d0]);
            const float2 m1v = *reinterpret_cast<const float2*>(&mrg[(r0 + 8) * 64 + d0]);
            float2 o0, o1;
            if (am0) o0 = make_float2(mnv[d0], mnv[d0 + 1]);
            else     o0 = make_float2((OC[nd][0] + m0v.x) * inv0, (OC[nd][1] + m0v.y) * inv0);
            if (am1) o1 = make_float2(mnv[d0], mnv[d0 + 1]);
            else     o1 = make_float2((OC[nd][2] + m1v.x) * inv1, (OC[nd][3] + m1v.y) * inv1);
            *reinterpret_cast<float2*>(&out[((size_t)b * S_ + qr0) * D_ + d0]) = o0;
            *reinterpret_cast<float2*>(&out[((size_t)b * S_ + qr1) * D_ + d0]) = o1;
        }
    }
}

// ---------------------------------------------------------------------------
extern "C" void kernel_launch(void* const* d_in, const int* in_sizes, int n_in,
                              void* d_out, int out_size)
{
    const float* E  = (const float*)d_in[0];
    const float* PK = (const float*)d_in[1];
    const float* PV = (const float*)d_in[2];
    const float* Wq = (const float*)d_in[3];
    const float* bq = (const float*)d_in[4];
    const float* Wk = (const float*)d_in[5];
    const float* bk = (const float*)d_in[6];
    const float* Wv = (const float*)d_in[7];
    const float* bv = (const float*)d_in[8];
    const void*  pad = d_in[9];
    float* out = (float*)d_out;

    cudaFuncSetAttribute(attn_mma_kernel, cudaFuncAttributeMaxDynamicSharedMemorySize, SM_TOTAL);

    proj_kernel<<<256, 256>>>(E, PK, PV, Wq, bq, Wk, bk, Wv, bv, pad);
    attn_mma_kernel<<<256, 256, SM_TOTAL>>>(out);
}

// round 13
// speedup vs baseline: 1.4130x; 1.4130x over previous
#include <cuda_runtime.h>
#include <cuda_fp16.h>
#include <math.h>
#include <stdint.h>

// Problem constants
constexpr int B_ = 4, S_ = 4096, D_ = 64;
constexpr int MT = 64;            // q rows per tile (one phase)
constexpr int NT = 128;           // keys per k-tile
constexpr float QSCALE = 0.18033688011112042f;  // 0.125 * log2(e), folded into Q

// ---- global scratch (allocation-free rule) ----
__device__ __align__(16) __half g_Qh[B_*S_*D_];
__device__ __align__(16) __half g_Kh[B_*S_*D_];   // zeroed on padded keys
__device__ __align__(16) __half g_Vh[B_*S_*D_];   // zeroed on padded keys
__device__ __align__(16) __half g_pad1h[B_*S_];   // 1.0 keep / 0.0 masked
__device__ float g_part[128][D_];                 // V_p column sums per proj CTA

__device__ __forceinline__ uint32_t smem_u32(const void* p) {
    uint32_t a;
    asm("{ .reg .u64 t; cvta.to.shared.u64 t, %1; cvt.u32.u64 %0, t; }" : "=r"(a) : "l"(p));
    return a;
}

// ---- mma.sync / ldmatrix / misc PTX ----
__device__ __forceinline__ void ldm_x4(uint32_t* r, uint32_t a) {
    asm volatile("ldmatrix.sync.aligned.m8n8.x4.shared.b16 {%0,%1,%2,%3}, [%4];"
                 : "=r"(r[0]), "=r"(r[1]), "=r"(r[2]), "=r"(r[3]) : "r"(a));
}
__device__ __forceinline__ void ldm_x4_t(uint32_t* r, uint32_t a) {
    asm volatile("ldmatrix.sync.aligned.m8n8.x4.trans.shared.b16 {%0,%1,%2,%3}, [%4];"
                 : "=r"(r[0]), "=r"(r[1]), "=r"(r[2]), "=r"(r[3]) : "r"(a));
}
__device__ __forceinline__ void mma_f16(float* c, const uint32_t* a, const uint32_t* b) {
    asm volatile("mma.sync.aligned.m16n8k16.row.col.f32.f16.f16.f32 "
                 "{%0,%1,%2,%3}, {%4,%5,%6,%7}, {%8,%9}, {%0,%1,%2,%3};"
                 : "+f"(c[0]), "+f"(c[1]), "+f"(c[2]), "+f"(c[3])
                 : "r"(a[0]), "r"(a[1]), "r"(a[2]), "r"(a[3]), "r"(b[0]), "r"(b[1]));
}
__device__ __forceinline__ float ex2(float x) {
    float y; asm("ex2.approx.f32 %0, %1;" : "=f"(y) : "f"(x)); return y;
}
// pack two fp32 -> fp16x2; second arg lands in the LOW half
__device__ __forceinline__ uint32_t cvt_f16x2(float hi, float lo) {
    uint32_t r; asm("cvt.rn.f16x2.f32 %0, %1, %2;" : "=r"(r) : "f"(hi), "f"(lo)); return r;
}
__device__ __forceinline__ uint32_t lds32(uint32_t a) {
    uint32_t v; asm volatile("ld.shared.b32 %0, [%1];" : "=r"(v) : "r"(a)); return v;
}
__device__ __forceinline__ void sts128(uint32_t a, uint32_t x, uint32_t y, uint32_t z, uint32_t w) {
    asm volatile("st.shared.v4.b32 [%0], {%1,%2,%3,%4};"
                 :: "r"(a), "r"(x), "r"(y), "r"(z), "r"(w) : "memory");
}
__device__ __forceinline__ void cpa16(uint32_t dst, const void* src) {
    asm volatile("cp.async.cg.shared.global [%0], [%1], 16;" :: "r"(dst), "l"(src));
}
#define CP_COMMIT() asm volatile("cp.async.commit_group;" ::: "memory")
#define CP_WAIT0()  asm volatile("cp.async.wait_group 0;" ::: "memory")

// ---------------------------------------------------------------------------
// Kernel 1: tensor-core QKV projection.
// D = E @ W^T emulated in fp32 precision by fp16 hi/lo (3 combos:
// Ehi*Whi + Elo*Whi + Ehi*Wlo), so Q/K/V match the fp32 reference to ~1e-6
// before their final fp16 rounding. Also: pad dtype detect + canonical half
// mask, padded-K/V zeroing, and per-CTA fp32 V_p column sums (meanV).
// 128 CTAs x 256 threads; CTA = 128 rows; warp = 16 rows.
// ---------------------------------------------------------------------------
constexpr int PSE_HI = 0;                       // E hi: 128 x 128B (swizzled)
constexpr int PSE_LO = 16384;                   // E lo
constexpr int PSW    = 32768;                   // W: 3 x (hi 8KB + lo 8KB)
constexpr int PROJ_SMEM = PSW + 3 * 16384;      // 81920

__global__ __launch_bounds__(256) void proj_kernel(
    const float* __restrict__ E,  const float* __restrict__ PK, const float* __restrict__ PV,
    const float* __restrict__ Wq, const float* __restrict__ bq,
    const float* __restrict__ Wk, const float* __restrict__ bk,
    const float* __restrict__ Wv, const float* __restrict__ bv,
    const void* __restrict__ pad)
{
    extern __shared__ char psm[];
    const uint32_t smb = smem_u32(psm);
    __shared__ float bsm[3][64];
    __shared__ float keepf[128];
    __shared__ float comb[128];
    __shared__ int f[2];
    const int t = threadIdx.x, wid = t >> 5, lane = t & 31;
    const int g8 = lane >> 3, l8 = lane & 7, l4 = lane >> 2, lq = lane & 3;
    const int bid = blockIdx.x;

    if (t < 2) f[t] = 0;
    if (t < 64) { bsm[0][t] = bq[t]; bsm[1][t] = bk[t]; bsm[2][t] = bv[t]; }

    // ---- stage E hi/lo (row = t>>1, half-row of 32 floats per thread) ----
    {
        const int row = t >> 1, half = t & 1;
        const float4* er = reinterpret_cast<const float4*>(
            E + ((size_t)bid * 128 + row) * 64 + half * 32);
        #pragma unroll
        for (int k = 0; k < 4; k++) {
            float4 va = er[2 * k], vb = er[2 * k + 1];
            float v[8] = {va.x, va.y, va.z, va.w, vb.x, vb.y, vb.z, vb.w};
            uint32_t uh[4], ul[4];
            #pragma unroll
            for (int j = 0; j < 4; j++) {
                const __half h0 = __float2half_rn(v[2*j]);
                const __half h1 = __float2half_rn(v[2*j+1]);
                const __half e0 = __float2half_rn(v[2*j]   - __half2float(h0));
                const __half e1 = __float2half_rn(v[2*j+1] - __half2float(h1));
                uh[j] = (uint32_t)__half_as_ushort(h0) | ((uint32_t)__half_as_ushort(h1) << 16);
                ul[j] = (uint32_t)__half_as_ushort(e0) | ((uint32_t)__half_as_ushort(e1) << 16);
            }
            const int c = half * 4 + k;
            const uint32_t sw = (uint32_t)row * 128 + (((uint32_t)(c ^ (row & 7))) << 4);
            sts128(smb + PSE_HI + sw, uh[0], uh[1], uh[2], uh[3]);
            sts128(smb + PSE_LO + sw, ul[0], ul[1], ul[2], ul[3]);
        }
    }

    // ---- stage W hi/lo (3 matrices x 64 rows x 2 half-rows = 384 units) ----
    {
        const float* Wsrc[3] = {Wq, Wk, Wv};
        #pragma unroll
        for (int u = t; u < 384; u += 256) {
            const int m = u >> 7, rem = u & 127, row = rem >> 1, half = rem & 1;
            const float4* wr4 = reinterpret_cast<const float4*>(Wsrc[m] + row * 64 + half * 32);
            #pragma unroll
            for (int k = 0; k < 4; k++) {
                float4 va = wr4[2 * k], vb = wr4[2 * k + 1];
                float v[8] = {va.x, va.y, va.z, va.w, vb.x, vb.y, vb.z, vb.w};
                uint32_t uh[4], ul[4];
                #pragma unroll
                for (int j = 0; j < 4; j++) {
                    const __half h0 = __float2half_rn(v[2*j]);
                    const __half h1 = __float2half_rn(v[2*j+1]);
                    const __half e0 = __float2half_rn(v[2*j]   - __half2float(h0));
                    const __half e1 = __float2half_rn(v[2*j+1] - __half2float(h1));
                    uh[j] = (uint32_t)__half_as_ushort(h0) | ((uint32_t)__half_as_ushort(h1) << 16);
                    ul[j] = (uint32_t)__half_as_ushort(e0) | ((uint32_t)__half_as_ushort(e1) << 16);
                }
                const int c = half * 4 + k;
                const uint32_t sw = (uint32_t)row * 128 + (((uint32_t)(c ^ (row & 7))) << 4);
                const uint32_t base = smb + PSW + m * 16384;
                sts128(base + sw, uh[0], uh[1], uh[2], uh[3]);
                sts128(base + 8192 + sw, ul[0], ul[1], ul[2], ul[3]);
            }
        }
    }

    // ---- pad dtype detection (16KB scan = minimum buffer size) ----
    {
        const uint4* p4 = reinterpret_cast<const uint4*>(pad);
        uint32_t ge2 = 0, odd = 0;
        #pragma unroll
        for (int i = t; i < 1024; i += 256) {
            uint4 v = p4[i];
            uint32_t o = v.x | v.y | v.z | v.w;
            ge2 |= o & 0xFEFEFEFEu;
            odd |= o & 0xFFFFFF00u;
        }
        if (ge2) atomicOr(&f[0], 1);
        if (odd) atomicOr(&f[1], 1);
    }
    __syncthreads();

    // ---- canonical half mask + keep flags for this CTA's 128 rows ----
    if (t < 128) {
        const int kind = f[0] ? 2 : (f[1] ? 0 : 1);   // 0=u8, 1=i32, 2=f32
        const int i = bid * 128 + t;
        bool m;
        if (kind == 0)      m = ((const unsigned char*)pad)[i] != 0;
        else if (kind == 1) m = ((const int*)pad)[i] != 0;
        else                m = ((const float*)pad)[i] != 0.f;
        const float k = m ? 0.f : 1.f;
        keepf[t] = k;
        g_pad1h[i] = __float2half(k);
    }
    __syncthreads();

    // ---- A fragments (E rows, hi/lo), 4 k-chunks of 16 ----
    uint32_t ah[4][4], al[4][4];
    {
        const int arow = wid * 16 + (g8 & 1) * 8 + l8;
        #pragma unroll
        for (int dc = 0; dc < 4; dc++) {
            const int c = 2 * dc + (g8 >> 1);
            const uint32_t a0 = smb + PSE_HI + arow * 128 + (((uint32_t)(c ^ (arow & 7))) << 4);
            ldm_x4(ah[dc], a0);
            ldm_x4(al[dc], a0 + (PSE_LO - PSE_HI));
        }
    }
    __syncthreads();   // all A-frag reads done before red overlays the E area

    const int r0l = wid * 16 + l4;                 // local rows r0l, r0l+8
    const size_t grow0 = (size_t)bid * 128 + r0l;
    const float keep0 = keepf[r0l], keep1 = keepf[r0l + 8];
    float* red = reinterpret_cast<float*>(psm + PSE_HI);   // 128 x 64 fp32 overlay

    __half* gdsts[3] = {g_Qh, g_Kh, g_Vh};

    #pragma unroll 1
    for (int m = 0; m < 3; m++) {
        float C[8][4];
        #pragma unroll
        for (int i = 0; i < 8; i++)
            { C[i][0] = 0.f; C[i][1] = 0.f; C[i][2] = 0.f; C[i][3] = 0.f; }
        const uint32_t wb = smb + PSW + m * 16384;

        #pragma unroll
        for (int nb = 0; nb < 4; nb++) {
            #pragma unroll
            for (int ks = 0; ks < 4; ks++) {
                const int row = nb * 16 + (g8 >> 1) * 8 + l8;
                const int c = 2 * ks + (g8 & 1);
                const uint32_t a = wb + row * 128 + (((uint32_t)(c ^ (row & 7))) << 4);
                uint32_t bh[4], bl[4];
                ldm_x4(bh, a);
                ldm_x4(bl, a + 8192);
                mma_f16(C[2*nb],   ah[ks], bh);
                mma_f16(C[2*nb],   al[ks], bh);
                mma_f16(C[2*nb],   ah[ks], bl);
                mma_f16(C[2*nb+1], ah[ks], bh + 2);
                mma_f16(C[2*nb+1], al[ks], bh + 2);
                mma_f16(C[2*nb+1], ah[ks], bl + 2);
            }
        }

        // ---- epilogue: bias + scale/modulate + keep-zero + fp16 store ----
        __half* gd = gdsts[m];
        #pragma unroll
        for (int i = 0; i < 8; i++) {
            const int c0 = i * 8 + 2 * lq;
            const float b0 = bsm[m][c0], b1 = bsm[m][c0 + 1];
            float v00 = C[i][0] + b0, v01 = C[i][1] + b1;
            float v10 = C[i][2] + b0, v11 = C[i][3] + b1;
            if (m == 0) {
                v00 *= QSCALE; v01 *= QSCALE; v10 *= QSCALE; v11 *= QSCALE;
            } else {
                const float* mod = (m == 1 ? PK : PV);
                const float2 m0 = *reinterpret_cast<const float2*>(mod + grow0 * 64 + c0);
                const float2 m1 = *reinterpret_cast<const float2*>(mod + (grow0 + 8) * 64 + c0);
                v00 *= m0.x; v01 *= m0.y; v10 *= m1.x; v11 *= m1.y;
                if (m == 2) {   // stash UN-zeroed fp32 V_p for meanV
                    *reinterpret_cast<float2*>(&red[r0l * 64 + c0])       = make_float2(v00, v01);
                    *reinterpret_cast<float2*>(&red[(r0l + 8) * 64 + c0]) = make_float2(v10, v11);
                }
                v00 *= keep0; v01 *= keep0; v10 *= keep1; v11 *= keep1;
            }
            *reinterpret_cast<uint32_t*>(&gd[grow0 * 64 + c0])       = cvt_f16x2(v01, v00);
            *reinterpret_cast<uint32_t*>(&gd[(grow0 + 8) * 64 + c0]) = cvt_f16x2(v11, v10);
        }
    }

    // ---- meanV partial for this CTA's 128 rows ----
    __syncthreads();
    if (t < 128) {
        const int col = t & 63, half = t >> 6;
        float a = 0.f;
        #pragma unroll 8
        for (int r = half * 64; r < half * 64 + 64; r++) a += red[r * 64 + col];
        comb[t] = a;
    }
    __syncthreads();
    if (t < 64) g_part[bid][t] = comb[t] + comb[t + 64];
}

// ---------------------------------------------------------------------------
// Kernel 2: single-fp16 mma.sync flash attention (round-11 measured-best).
// CTA = 256 threads = 4 row-warps x 2 key-halves over a 64-row q-tile.
// Two-phase pair scheduling (qt, 63-qt): exactly 33 k-tiles per CTA.
// Padding folded into the GEMMs (zeroed K/V + ones-mask MMA for l).
// ---------------------------------------------------------------------------
constexpr int SM_QH   = 0;                      // 64 x 128B
constexpr int SM_KV   = 8192;                   // 2 stages x (K 16KB + V 16KB)
constexpr int STG_SZ  = 32768;
constexpr int OFF_K   = 0, OFF_V = 16384;
constexpr int SM_PADB = SM_KV + 2 * STG_SZ;     // 73728, 2 x 256B (half mask)
constexpr int SM_LSM  = SM_PADB + 512;          // 74240, 2 x 64 f32
constexpr int SM_MNV  = SM_LSM + 512;           // 74752, 64 f32
constexpr int SM_MRG  = SM_KV;                  // merge overlays stage 0 (drained)
constexpr int SM_TOTAL = SM_MNV + 256;          // 75008

__global__ __launch_bounds__(256, 1) void attn_mma_kernel(float* __restrict__ out)
{
    extern __shared__ char sm[];
    const uint32_t smb = smem_u32(sm);
    const int tid = threadIdx.x, wid = tid >> 5, lane = tid & 31;
    const int wr = wid & 3, wc = wid >> 2;        // row-warp, key-half
    const int b = blockIdx.y;
    const int g8 = lane >> 3, l8 = lane & 7, l4 = lane >> 2, lq = lane & 3;
    float* lsm  = reinterpret_cast<float*>(sm + SM_LSM);
    float* mnv  = reinterpret_cast<float*>(sm + SM_MNV);
    float* mrg  = reinterpret_cast<float*>(sm + SM_MRG);

    // ---- meanV for this batch (sum of 32 proj-CTA partials) ----
    if (tid < 64) {
        float a = 0.f;
        #pragma unroll 8
        for (int i = 0; i < 32; i++) a += g_part[b * 32 + i][tid];
        mnv[tid] = a * (1.0f / (float)S_);
    }

    #pragma unroll 1
    for (int phase = 0; phase < 2; phase++) {
        const int qt = phase ? (63 - blockIdx.x) : blockIdx.x;
        const int qbase = qt * MT;
        const int nkt = (qt >> 1) + 1;

        __syncthreads();   // prev phase merge reads done (and mnv visible)

        // ---- prologue: async-copy Q + k-tile 0 into stage 0 ----
        {
            const uint4* qh4 = reinterpret_cast<const uint4*>(g_Qh + ((size_t)b * S_ + qbase) * D_);
            #pragma unroll
            for (int it = 0; it < 2; it++) {
                int i = tid + it * 256;
                int row = i >> 3, c = i & 7;
                uint32_t sw = row * 128 + (((uint32_t)(c ^ (row & 7))) << 4);
                cpa16(smb + SM_QH + sw, qh4 + i);
            }
            const __half* srcs[2] = {g_Kh + (size_t)b * S_ * D_, g_Vh + (size_t)b * S_ * D_};
            #pragma unroll
            for (int t2 = 0; t2 < 2; t2++) {
                #pragma unroll
                for (int it = 0; it < 4; it++) {
                    int i = tid + it * 256;
                    int row = i >> 3, c = i & 7;
                    uint32_t dst = smb + SM_KV + t2 * 16384 + row * 128 + (((uint32_t)(c ^ (row & 7))) << 4);
                    cpa16(dst, reinterpret_cast<const uint4*>(srcs[t2]) + i);
                }
            }
            if (tid < 16)
                cpa16(smb + SM_PADB + tid * 16, (const char*)(g_pad1h + b * S_) + tid * 16);
            CP_COMMIT();
        }
        CP_WAIT0();
        __syncthreads();

        // ---- Q A-fragments, 4 d-chunks of 16 ----
        uint32_t qh[4][4];
        {
            const int row = wr * 16 + (g8 & 1) * 8 + l8;
            #pragma unroll
            for (int dc = 0; dc < 4; dc++) {
                const int c = 2 * dc + (g8 >> 1);
                ldm_x4(qh[dc], smb + SM_QH + row * 128 + (((uint32_t)(c ^ (row & 7))) << 4));
            }
        }

        float OC[8][4];
        #pragma unroll
        for (int i = 0; i < 8; i++)
            { OC[i][0] = 0.f; OC[i][1] = 0.f; OC[i][2] = 0.f; OC[i][3] = 0.f; }
        float LM[4] = {0.f, 0.f, 0.f, 0.f};
        const int q0 = qbase + wr * 16 + l4, q1 = q0 + 8;
        const int kb0 = wc * 64;

        #pragma unroll 1
        for (int j = 0; j < nkt; j++) {
            const int st = j & 1;
            const uint32_t stb = smb + SM_KV + st * STG_SZ;
            const uint32_t padb = smb + SM_PADB + st * 256;
            const int kt = j * NT;

            if (j + 1 < nkt) {
                const int ktn = (j + 1) * NT;
                const uint32_t nstb = smb + SM_KV + ((j + 1) & 1) * STG_SZ;
                const __half* srcs[2] = {g_Kh + ((size_t)b * S_ + ktn) * D_,
                                         g_Vh + ((size_t)b * S_ + ktn) * D_};
                #pragma unroll
                for (int t2 = 0; t2 < 2; t2++) {
                    #pragma unroll
                    for (int it = 0; it < 4; it++) {
                        int i = tid + it * 256;
                        int row = i >> 3, c = i & 7;
                        uint32_t dst = nstb + t2 * 16384 + row * 128 + (((uint32_t)(c ^ (row & 7))) << 4);
                        cpa16(dst, reinterpret_cast<const uint4*>(srcs[t2]) + i);
                    }
                }
                if (tid < 16)
                    cpa16(smb + SM_PADB + ((j + 1) & 1) * 256 + tid * 16,
                          (const char*)(g_pad1h + b * S_ + ktn) + tid * 16);
                CP_COMMIT();
            }

            // ---- S = Q K^T (single fp16) ----
            float SC[8][4];
            #pragma unroll
            for (int i = 0; i < 8; i++)
                { SC[i][0] = 0.f; SC[i][1] = 0.f; SC[i][2] = 0.f; SC[i][3] = 0.f; }
            {
                const int krow0 = kb0 + (g8 >> 1) * 8 + l8;
                #pragma unroll
                for (int dc = 0; dc < 4; dc++) {
                    #pragma unroll
                    for (int kp = 0; kp < 4; kp++) {
                        const int row = krow0 + kp * 16;
                        const int c = 2 * dc + (g8 & 1);
                        uint32_t bh[4];
                        ldm_x4(bh, stb + OFF_K + row * 128 + (((uint32_t)(c ^ (row & 7))) << 4));
                        mma_f16(SC[2*kp],   qh[dc], bh);
                        mma_f16(SC[2*kp+1], qh[dc], bh + 2);
                    }
                }
            }

            // ---- ex2 + C->A fragment conversion ----
            uint32_t Ph[4][4];
            if (j < nkt - 1) {
                #pragma unroll
                for (int n = 0; n < 8; n++) {
                    const float p00 = ex2(SC[n][0]);
                    const float p01 = ex2(SC[n][1]);
                    const float p10 = ex2(SC[n][2]);
                    const float p11 = ex2(SC[n][3]);
                    const int kc = n >> 1, sub = (n & 1) * 2;
                    Ph[kc][sub]     = cvt_f16x2(p01, p00);
                    Ph[kc][sub + 1] = cvt_f16x2(p11, p10);
                }
            } else {
                #pragma unroll
                for (int n = 0; n < 8; n++) {
                    const int key = kt + kb0 + n * 8 + 2 * lq;
                    const float p00 = (key     <= q0) ? ex2(SC[n][0]) : 0.f;
                    const float p01 = (key + 1 <= q0) ? ex2(SC[n][1]) : 0.f;
                    const float p10 = (key     <= q1) ? ex2(SC[n][2]) : 0.f;
                    const float p11 = (key + 1 <= q1) ? ex2(SC[n][3]) : 0.f;
                    const int kc = n >> 1, sub = (n & 1) * 2;
                    Ph[kc][sub]     = cvt_f16x2(p01, p00);
                    Ph[kc][sub + 1] = cvt_f16x2(p11, p10);
                }
            }

            // ---- l += P . mask ----
            {
                #pragma unroll
                for (int kc = 0; kc < 4; kc++) {
                    const uint32_t a = padb + (uint32_t)(kb0 + kc * 16 + 2 * lq) * 2;
                    uint32_t bm[2];
                    bm[0] = lds32(a);
                    bm[1] = lds32(a + 16);
                    mma_f16(LM, Ph[kc], bm);
                }
            }

            // ---- O += P V ----
            {
                const int vrow0 = kb0 + (g8 & 1) * 8 + l8;
                #pragma unroll
                for (int kc = 0; kc < 4; kc++) {
                    #pragma unroll
                    for (int ndp = 0; ndp < 4; ndp++) {
                        const int row = vrow0 + kc * 16;
                        const int c = 2 * ndp + (g8 >> 1);
                        uint32_t bh[4];
                        ldm_x4_t(bh, stb + OFF_V + row * 128 + (((uint32_t)(c ^ (row & 7))) << 4));
                        mma_f16(OC[2*ndp],   Ph[kc], bh);
                        mma_f16(OC[2*ndp+1], Ph[kc], bh + 2);
                    }
                }
            }

            if (j + 1 < nkt) CP_WAIT0();
            __syncthreads();
        }

        // ---- merge the two key-halves ----
        if (lq == 0) {
            lsm[wc * 64 + wr * 16 + l4]     = LM[0];
            lsm[wc * 64 + wr * 16 + 8 + l4] = LM[2];
        }
        if (wc == 1) {
            const int r0 = wr * 16 + l4;
            #pragma unroll
            for (int nd = 0; nd < 8; nd++) {
                const int d0 = nd * 8 + 2 * lq;
                *reinterpret_cast<float2*>(&mrg[r0 * 64 + d0])       = make_float2(OC[nd][0], OC[nd][1]);
                *reinterpret_cast<float2*>(&mrg[(r0 + 8) * 64 + d0]) = make_float2(OC[nd][2], OC[nd][3]);
            }
        }
        __syncthreads();
        if (wc == 0) {
            const int r0 = wr * 16 + l4;
            const float lt0 = lsm[r0] + lsm[64 + r0];
            const float lt1 = lsm[r0 + 8] + lsm[64 + r0 + 8];
            const bool am0 = (lt0 == 0.f), am1 = (lt1 == 0.f);
            const float inv0 = am0 ? 0.f : 1.f / lt0;
            const float inv1 = am1 ? 0.f : 1.f / lt1;
            const int qr0 = qbase + r0, qr1 = qr0 + 8;
            #pragma unroll
            for (int nd = 0; nd < 8; nd++) {
                const int d0 = nd * 8 + 2 * lq;
                const float2 m0v = *reinterpret_cast<const float2*>(&mrg[r0 * 64 + d0]);
                const float2 m1v = *reinterpret_cast<const float2*>(&mrg[(r0 + 8) * 64 + d0]);
                float2 o0, o1;
                if (am0) o0 = make_float2(mnv[d0], mnv[d0 + 1]);
                else     o0 = make_float2((OC[nd][0] + m0v.x) * inv0, (OC[nd][1] + m0v.y) * inv0);
                if (am1) o1 = make_float2(mnv[d0], mnv[d0 + 1]);
                else     o1 = make_float2((OC[nd][2] + m1v.x) * inv1, (OC[nd][3] + m1v.y) * inv1);
                *reinterpret_cast<float2*>(&out[((size_t)b * S_ + qr0) * D_ + d0]) = o0;
                *reinterpret_cast<float2*>(&out[((size_t)b * S_ + qr1) * D_ + d0]) = o1;
            }
        }
    }
}

// ---------------------------------------------------------------------------
extern "C" void kernel_launch(void* const* d_in, const int* in_sizes, int n_in,
                              void* d_out, int out_size)
{
    const float* E  = (const float*)d_in[0];
    const float* PK = (const float*)d_in[1];
    const float* PV = (const float*)d_in[2];
    const float* Wq = (const float*)d_in[3];
    const float* bq = (const float*)d_in[4];
    const float* Wk = (const float*)d_in[5];
    const float* bk = (const float*)d_in[6];
    const float* Wv = (const float*)d_in[7];
    const float* bv = (const float*)d_in[8];
    const void*  pad = d_in[9];
    float* out = (float*)d_out;

    cudaFuncSetAttribute(proj_kernel, cudaFuncAttributeMaxDynamicSharedMemorySize, PROJ_SMEM);
    cudaFuncSetAttribute(attn_mma_kernel, cudaFuncAttributeMaxDynamicSharedMemorySize, SM_TOTAL);

    proj_kernel<<<128, 256, PROJ_SMEM>>>(E, PK, PV, Wq, bq, Wk, bk, Wv, bv, pad);
    attn_mma_kernel<<<dim3(32, B_), 256, SM_TOTAL>>>(out);
}

// round 14
// speedup vs baseline: 1.4654x; 1.0371x over previous
#include <cuda_runtime.h>
#include <cuda_fp16.h>
#include <math.h>
#include <stdint.h>

// Problem constants
constexpr int B_ = 4, S_ = 4096, D_ = 64;
constexpr int MT = 64;            // q rows per tile (one phase)
constexpr int NT = 128;           // keys per k-tile
constexpr float QSCALE = 0.18033688011112042f;  // 0.125 * log2(e), folded into Q

// ---- global scratch (allocation-free rule) ----
__device__ __align__(16) __half g_Qh[B_*S_*D_];
__device__ __align__(16) __half g_Kh[B_*S_*D_];   // zeroed on padded keys
__device__ __align__(16) __half g_Vh[B_*S_*D_];   // zeroed on padded keys
__device__ __align__(16) __half g_pad1h[B_*S_];   // 1.0 keep / 0.0 masked
__device__ float g_part[128][D_];                 // V_p column sums per proj CTA

__device__ __forceinline__ uint32_t smem_u32(const void* p) {
    uint32_t a;
    asm("{ .reg .u64 t; cvta.to.shared.u64 t, %1; cvt.u32.u64 %0, t; }" : "=r"(a) : "l"(p));
    return a;
}

// ---- mma.sync / ldmatrix / misc PTX ----
__device__ __forceinline__ void ldm_x4(uint32_t* r, uint32_t a) {
    asm volatile("ldmatrix.sync.aligned.m8n8.x4.shared.b16 {%0,%1,%2,%3}, [%4];"
                 : "=r"(r[0]), "=r"(r[1]), "=r"(r[2]), "=r"(r[3]) : "r"(a));
}
__device__ __forceinline__ void ldm_x4_t(uint32_t* r, uint32_t a) {
    asm volatile("ldmatrix.sync.aligned.m8n8.x4.trans.shared.b16 {%0,%1,%2,%3}, [%4];"
                 : "=r"(r[0]), "=r"(r[1]), "=r"(r[2]), "=r"(r[3]) : "r"(a));
}
__device__ __forceinline__ void mma_f16(float* c, const uint32_t* a, const uint32_t* b) {
    asm volatile("mma.sync.aligned.m16n8k16.row.col.f32.f16.f16.f32 "
                 "{%0,%1,%2,%3}, {%4,%5,%6,%7}, {%8,%9}, {%0,%1,%2,%3};"
                 : "+f"(c[0]), "+f"(c[1]), "+f"(c[2]), "+f"(c[3])
                 : "r"(a[0]), "r"(a[1]), "r"(a[2]), "r"(a[3]), "r"(b[0]), "r"(b[1]));
}
__device__ __forceinline__ float ex2(float x) {
    float y; asm("ex2.approx.f32 %0, %1;" : "=f"(y) : "f"(x)); return y;
}
// pack two fp32 -> fp16x2; second arg lands in the LOW half
__device__ __forceinline__ uint32_t cvt_f16x2(float hi, float lo) {
    uint32_t r; asm("cvt.rn.f16x2.f32 %0, %1, %2;" : "=r"(r) : "f"(hi), "f"(lo)); return r;
}
__device__ __forceinline__ uint32_t lds32(uint32_t a) {
    uint32_t v; asm volatile("ld.shared.b32 %0, [%1];" : "=r"(v) : "r"(a)); return v;
}
__device__ __forceinline__ void sts128(uint32_t a, uint32_t x, uint32_t y, uint32_t z, uint32_t w) {
    asm volatile("st.shared.v4.b32 [%0], {%1,%2,%3,%4};"
                 :: "r"(a), "r"(x), "r"(y), "r"(z), "r"(w) : "memory");
}
__device__ __forceinline__ void cpa16(uint32_t dst, const void* src) {
    asm volatile("cp.async.cg.shared.global [%0], [%1], 16;" :: "r"(dst), "l"(src));
}
#define CP_COMMIT() asm volatile("cp.async.commit_group;" ::: "memory")
#define CP_WAIT0()  asm volatile("cp.async.wait_group 0;" ::: "memory")

// ---------------------------------------------------------------------------
// Kernel 1: tensor-core QKV projection (round-13 measured-best, unchanged).
// D = E @ W^T emulated in fp32 precision by fp16 hi/lo (3 combos).
// Also: pad dtype detect + canonical half mask, padded-K/V zeroing, and
// per-CTA fp32 V_p column sums (meanV). 128 CTAs x 256 threads.
// ---------------------------------------------------------------------------
constexpr int PSE_HI = 0;                       // E hi: 128 x 128B (swizzled)
constexpr int PSE_LO = 16384;                   // E lo
constexpr int PSW    = 32768;                   // W: 3 x (hi 8KB + lo 8KB)
constexpr int PROJ_SMEM = PSW + 3 * 16384;      // 81920

__global__ __launch_bounds__(256) void proj_kernel(
    const float* __restrict__ E,  const float* __restrict__ PK, const float* __restrict__ PV,
    const float* __restrict__ Wq, const float* __restrict__ bq,
    const float* __restrict__ Wk, const float* __restrict__ bk,
    const float* __restrict__ Wv, const float* __restrict__ bv,
    const void* __restrict__ pad)
{
    extern __shared__ char psm[];
    const uint32_t smb = smem_u32(psm);
    __shared__ float bsm[3][64];
    __shared__ float keepf[128];
    __shared__ float comb[128];
    __shared__ int f[2];
    const int t = threadIdx.x, wid = t >> 5, lane = t & 31;
    const int g8 = lane >> 3, l8 = lane & 7, l4 = lane >> 2, lq = lane & 3;
    const int bid = blockIdx.x;

    if (t < 2) f[t] = 0;
    if (t < 64) { bsm[0][t] = bq[t]; bsm[1][t] = bk[t]; bsm[2][t] = bv[t]; }

    // ---- stage E hi/lo (row = t>>1, half-row of 32 floats per thread) ----
    {
        const int row = t >> 1, half = t & 1;
        const float4* er = reinterpret_cast<const float4*>(
            E + ((size_t)bid * 128 + row) * 64 + half * 32);
        #pragma unroll
        for (int k = 0; k < 4; k++) {
            float4 va = er[2 * k], vb = er[2 * k + 1];
            float v[8] = {va.x, va.y, va.z, va.w, vb.x, vb.y, vb.z, vb.w};
            uint32_t uh[4], ul[4];
            #pragma unroll
            for (int j = 0; j < 4; j++) {
                const __half h0 = __float2half_rn(v[2*j]);
                const __half h1 = __float2half_rn(v[2*j+1]);
                const __half e0 = __float2half_rn(v[2*j]   - __half2float(h0));
                const __half e1 = __float2half_rn(v[2*j+1] - __half2float(h1));
                uh[j] = (uint32_t)__half_as_ushort(h0) | ((uint32_t)__half_as_ushort(h1) << 16);
                ul[j] = (uint32_t)__half_as_ushort(e0) | ((uint32_t)__half_as_ushort(e1) << 16);
            }
            const int c = half * 4 + k;
            const uint32_t sw = (uint32_t)row * 128 + (((uint32_t)(c ^ (row & 7))) << 4);
            sts128(smb + PSE_HI + sw, uh[0], uh[1], uh[2], uh[3]);
            sts128(smb + PSE_LO + sw, ul[0], ul[1], ul[2], ul[3]);
        }
    }

    // ---- stage W hi/lo (3 matrices x 64 rows x 2 half-rows = 384 units) ----
    {
        const float* Wsrc[3] = {Wq, Wk, Wv};
        #pragma unroll
        for (int u = t; u < 384; u += 256) {
            const int m = u >> 7, rem = u & 127, row = rem >> 1, half = rem & 1;
            const float4* wr4 = reinterpret_cast<const float4*>(Wsrc[m] + row * 64 + half * 32);
            #pragma unroll
            for (int k = 0; k < 4; k++) {
                float4 va = wr4[2 * k], vb = wr4[2 * k + 1];
                float v[8] = {va.x, va.y, va.z, va.w, vb.x, vb.y, vb.z, vb.w};
                uint32_t uh[4], ul[4];
                #pragma unroll
                for (int j = 0; j < 4; j++) {
                    const __half h0 = __float2half_rn(v[2*j]);
                    const __half h1 = __float2half_rn(v[2*j+1]);
                    const __half e0 = __float2half_rn(v[2*j]   - __half2float(h0));
                    const __half e1 = __float2half_rn(v[2*j+1] - __half2float(h1));
                    uh[j] = (uint32_t)__half_as_ushort(h0) | ((uint32_t)__half_as_ushort(h1) << 16);
                    ul[j] = (uint32_t)__half_as_ushort(e0) | ((uint32_t)__half_as_ushort(e1) << 16);
                }
                const int c = half * 4 + k;
                const uint32_t sw = (uint32_t)row * 128 + (((uint32_t)(c ^ (row & 7))) << 4);
                const uint32_t base = smb + PSW + m * 16384;
                sts128(base + sw, uh[0], uh[1], uh[2], uh[3]);
                sts128(base + 8192 + sw, ul[0], ul[1], ul[2], ul[3]);
            }
        }
    }

    // ---- pad dtype detection (16KB scan = minimum buffer size) ----
    {
        const uint4* p4 = reinterpret_cast<const uint4*>(pad);
        uint32_t ge2 = 0, odd = 0;
        #pragma unroll
        for (int i = t; i < 1024; i += 256) {
            uint4 v = p4[i];
            uint32_t o = v.x | v.y | v.z | v.w;
            ge2 |= o & 0xFEFEFEFEu;
            odd |= o & 0xFFFFFF00u;
        }
        if (ge2) atomicOr(&f[0], 1);
        if (odd) atomicOr(&f[1], 1);
    }
    __syncthreads();

    // ---- canonical half mask + keep flags for this CTA's 128 rows ----
    if (t < 128) {
        const int kind = f[0] ? 2 : (f[1] ? 0 : 1);   // 0=u8, 1=i32, 2=f32
        const int i = bid * 128 + t;
        bool m;
        if (kind == 0)      m = ((const unsigned char*)pad)[i] != 0;
        else if (kind == 1) m = ((const int*)pad)[i] != 0;
        else                m = ((const float*)pad)[i] != 0.f;
        const float k = m ? 0.f : 1.f;
        keepf[t] = k;
        g_pad1h[i] = __float2half(k);
    }
    __syncthreads();

    // ---- A fragments (E rows, hi/lo), 4 k-chunks of 16 ----
    uint32_t ah[4][4], al[4][4];
    {
        const int arow = wid * 16 + (g8 & 1) * 8 + l8;
        #pragma unroll
        for (int dc = 0; dc < 4; dc++) {
            const int c = 2 * dc + (g8 >> 1);
            const uint32_t a0 = smb + PSE_HI + arow * 128 + (((uint32_t)(c ^ (arow & 7))) << 4);
            ldm_x4(ah[dc], a0);
            ldm_x4(al[dc], a0 + (PSE_LO - PSE_HI));
        }
    }
    __syncthreads();   // all A-frag reads done before red overlays the E area

    const int r0l = wid * 16 + l4;                 // local rows r0l, r0l+8
    const size_t grow0 = (size_t)bid * 128 + r0l;
    const float keep0 = keepf[r0l], keep1 = keepf[r0l + 8];
    float* red = reinterpret_cast<float*>(psm + PSE_HI);   // 128 x 64 fp32 overlay

    __half* gdsts[3] = {g_Qh, g_Kh, g_Vh};

    #pragma unroll 1
    for (int m = 0; m < 3; m++) {
        float C[8][4];
        #pragma unroll
        for (int i = 0; i < 8; i++)
            { C[i][0] = 0.f; C[i][1] = 0.f; C[i][2] = 0.f; C[i][3] = 0.f; }
        const uint32_t wb = smb + PSW + m * 16384;

        #pragma unroll
        for (int nb = 0; nb < 4; nb++) {
            #pragma unroll
            for (int ks = 0; ks < 4; ks++) {
                const int row = nb * 16 + (g8 >> 1) * 8 + l8;
                const int c = 2 * ks + (g8 & 1);
                const uint32_t a = wb + row * 128 + (((uint32_t)(c ^ (row & 7))) << 4);
                uint32_t bh[4], bl[4];
                ldm_x4(bh, a);
                ldm_x4(bl, a + 8192);
                mma_f16(C[2*nb],   ah[ks], bh);
                mma_f16(C[2*nb],   al[ks], bh);
                mma_f16(C[2*nb],   ah[ks], bl);
                mma_f16(C[2*nb+1], ah[ks], bh + 2);
                mma_f16(C[2*nb+1], al[ks], bh + 2);
                mma_f16(C[2*nb+1], ah[ks], bl + 2);
            }
        }

        // ---- epilogue: bias + scale/modulate + keep-zero + fp16 store ----
        __half* gd = gdsts[m];
        #pragma unroll
        for (int i = 0; i < 8; i++) {
            const int c0 = i * 8 + 2 * lq;
            const float b0 = bsm[m][c0], b1 = bsm[m][c0 + 1];
            float v00 = C[i][0] + b0, v01 = C[i][1] + b1;
            float v10 = C[i][2] + b0, v11 = C[i][3] + b1;
            if (m == 0) {
                v00 *= QSCALE; v01 *= QSCALE; v10 *= QSCALE; v11 *= QSCALE;
            } else {
                const float* mod = (m == 1 ? PK : PV);
                const float2 m0 = *reinterpret_cast<const float2*>(mod + grow0 * 64 + c0);
                const float2 m1 = *reinterpret_cast<const float2*>(mod + (grow0 + 8) * 64 + c0);
                v00 *= m0.x; v01 *= m0.y; v10 *= m1.x; v11 *= m1.y;
                if (m == 2) {   // stash UN-zeroed fp32 V_p for meanV
                    *reinterpret_cast<float2*>(&red[r0l * 64 + c0])       = make_float2(v00, v01);
                    *reinterpret_cast<float2*>(&red[(r0l + 8) * 64 + c0]) = make_float2(v10, v11);
                }
                v00 *= keep0; v01 *= keep0; v10 *= keep1; v11 *= keep1;
            }
            *reinterpret_cast<uint32_t*>(&gd[grow0 * 64 + c0])       = cvt_f16x2(v01, v00);
            *reinterpret_cast<uint32_t*>(&gd[(grow0 + 8) * 64 + c0]) = cvt_f16x2(v11, v10);
        }
    }

    // ---- meanV partial for this CTA's 128 rows ----
    __syncthreads();
    if (t < 128) {
        const int col = t & 63, half = t >> 6;
        float a = 0.f;
        #pragma unroll 8
        for (int r = half * 64; r < half * 64 + 64; r++) a += red[r * 64 + col];
        comb[t] = a;
    }
    __syncthreads();
    if (t < 64) g_part[bid][t] = comb[t] + comb[t + 64];
}

// ---------------------------------------------------------------------------
// Kernel 2: single-fp16 mma.sync flash attention, cp.async double-buffered.
// CTA = 256 threads = 2 row-groups (32 q-rows) x 4 key-quarters (32 keys):
// halves the per-tile ldmatrix smem traffic vs 4x2 (each warp reads 4KB of
// K and 4KB of V per tile instead of 8+8). Two-phase pair scheduling
// (qt, 63-qt): exactly 33 k-tiles per CTA. Padding folded into the GEMMs
// (zeroed K/V + ones-mask MMA for l). 4-way merge through drained stage smem.
// ---------------------------------------------------------------------------
constexpr int SM_QH   = 0;                      // 64 x 128B
constexpr int SM_KV   = 8192;                   // 2 stages x (K 16KB + V 16KB)
constexpr int STG_SZ  = 32768;
constexpr int OFF_K   = 0, OFF_V = 16384;
constexpr int SM_PADB = SM_KV + 2 * STG_SZ;     // 73728, 2 x 256B (half mask)
constexpr int SM_LSM  = SM_PADB + 512;          // 74240, 4 x 64 f32
constexpr int SM_MNV  = SM_LSM + 1024;          // 75264, 64 f32
constexpr int SM_MRG  = SM_KV;                  // merge overlays stages (drained)
constexpr int SM_TOTAL = SM_MNV + 256;          // 75520

__global__ __launch_bounds__(256, 1) void attn_mma_kernel(float* __restrict__ out)
{
    extern __shared__ char sm[];
    const uint32_t smb = smem_u32(sm);
    const int tid = threadIdx.x, wid = tid >> 5, lane = tid & 31;
    const int rg = wid & 1, wc = wid >> 1;        // row-group (0..1), key-quarter (0..3)
    const int b = blockIdx.y;
    const int g8 = lane >> 3, l8 = lane & 7, l4 = lane >> 2, lq = lane & 3;
    float* lsm  = reinterpret_cast<float*>(sm + SM_LSM);
    float* mnv  = reinterpret_cast<float*>(sm + SM_MNV);
    float* mrg  = reinterpret_cast<float*>(sm + SM_MRG);

    // ---- meanV for this batch (sum of 32 proj-CTA partials) ----
    if (tid < 64) {
        float a = 0.f;
        #pragma unroll 8
        for (int i = 0; i < 32; i++) a += g_part[b * 32 + i][tid];
        mnv[tid] = a * (1.0f / (float)S_);
    }

    #pragma unroll 1
    for (int phase = 0; phase < 2; phase++) {
        const int qt = phase ? (63 - blockIdx.x) : blockIdx.x;
        const int qbase = qt * MT;
        const int nkt = (qt >> 1) + 1;

        __syncthreads();   // prev phase merge reads done (and mnv visible)

        // ---- prologue: async-copy Q + k-tile 0 into stage 0 ----
        {
            const uint4* qh4 = reinterpret_cast<const uint4*>(g_Qh + ((size_t)b * S_ + qbase) * D_);
            #pragma unroll
            for (int it = 0; it < 2; it++) {
                int i = tid + it * 256;
                int row = i >> 3, c = i & 7;
                uint32_t sw = row * 128 + (((uint32_t)(c ^ (row & 7))) << 4);
                cpa16(smb + SM_QH + sw, qh4 + i);
            }
            const __half* srcs[2] = {g_Kh + (size_t)b * S_ * D_, g_Vh + (size_t)b * S_ * D_};
            #pragma unroll
            for (int t2 = 0; t2 < 2; t2++) {
                #pragma unroll
                for (int it = 0; it < 4; it++) {
                    int i = tid + it * 256;
                    int row = i >> 3, c = i & 7;
                    uint32_t dst = smb + SM_KV + t2 * 16384 + row * 128 + (((uint32_t)(c ^ (row & 7))) << 4);
                    cpa16(dst, reinterpret_cast<const uint4*>(srcs[t2]) + i);
                }
            }
            if (tid < 16)
                cpa16(smb + SM_PADB + tid * 16, (const char*)(g_pad1h + b * S_) + tid * 16);
            CP_COMMIT();
        }
        CP_WAIT0();
        __syncthreads();

        // ---- Q A-fragments: 2 row-chunks x 4 d-chunks ----
        uint32_t qh[2][4][4];
        #pragma unroll
        for (int rc = 0; rc < 2; rc++) {
            const int row = rg * 32 + rc * 16 + (g8 & 1) * 8 + l8;
            #pragma unroll
            for (int dc = 0; dc < 4; dc++) {
                const int c = 2 * dc + (g8 >> 1);
                ldm_x4(qh[rc][dc], smb + SM_QH + row * 128 + (((uint32_t)(c ^ (row & 7))) << 4));
            }
        }

        float OC[2][8][4];
        #pragma unroll
        for (int rc = 0; rc < 2; rc++)
            #pragma unroll
            for (int i = 0; i < 8; i++)
                { OC[rc][i][0] = 0.f; OC[rc][i][1] = 0.f; OC[rc][i][2] = 0.f; OC[rc][i][3] = 0.f; }
        float LM[2][4] = {{0.f,0.f,0.f,0.f},{0.f,0.f,0.f,0.f}};
        const int kb0 = wc * 32;

        #pragma unroll 1
        for (int j = 0; j < nkt; j++) {
            const int st = j & 1;
            const uint32_t stb = smb + SM_KV + st * STG_SZ;
            const uint32_t padb = smb + SM_PADB + st * 256;
            const int kt = j * NT;

            if (j + 1 < nkt) {
                const int ktn = (j + 1) * NT;
                const uint32_t nstb = smb + SM_KV + ((j + 1) & 1) * STG_SZ;
                const __half* srcs[2] = {g_Kh + ((size_t)b * S_ + ktn) * D_,
                                         g_Vh + ((size_t)b * S_ + ktn) * D_};
                #pragma unroll
                for (int t2 = 0; t2 < 2; t2++) {
                    #pragma unroll
                    for (int it = 0; it < 4; it++) {
                        int i = tid + it * 256;
                        int row = i >> 3, c = i & 7;
                        uint32_t dst = nstb + t2 * 16384 + row * 128 + (((uint32_t)(c ^ (row & 7))) << 4);
                        cpa16(dst, reinterpret_cast<const uint4*>(srcs[t2]) + i);
                    }
                }
                if (tid < 16)
                    cpa16(smb + SM_PADB + ((j + 1) & 1) * 256 + tid * 16,
                          (const char*)(g_pad1h + b * S_ + ktn) + tid * 16);
                CP_COMMIT();
            }

            const bool interior = (j < nkt - 1);

            #pragma unroll
            for (int kp = 0; kp < 2; kp++) {
                // ---- S = Q K^T for this 16-key chunk ----
                float SC[2][2][4];
                #pragma unroll
                for (int rc = 0; rc < 2; rc++)
                    #pragma unroll
                    for (int n = 0; n < 2; n++)
                        { SC[rc][n][0]=0.f; SC[rc][n][1]=0.f; SC[rc][n][2]=0.f; SC[rc][n][3]=0.f; }
                {
                    const int krow = kb0 + kp * 16 + (g8 >> 1) * 8 + l8;
                    #pragma unroll
                    for (int dc = 0; dc < 4; dc++) {
                        const int c = 2 * dc + (g8 & 1);
                        uint32_t bh[4];
                        ldm_x4(bh, stb + OFF_K + krow * 128 + (((uint32_t)(c ^ (krow & 7))) << 4));
                        #pragma unroll
                        for (int rc = 0; rc < 2; rc++) {
                            mma_f16(SC[rc][0], qh[rc][dc], bh);
                            mma_f16(SC[rc][1], qh[rc][dc], bh + 2);
                        }
                    }
                }

                // ---- ex2 + C->A fragment conversion ----
                uint32_t Ph[2][4];
                if (interior) {
                    #pragma unroll
                    for (int rc = 0; rc < 2; rc++)
                        #pragma unroll
                        for (int n = 0; n < 2; n++) {
                            const float p00 = ex2(SC[rc][n][0]);
                            const float p01 = ex2(SC[rc][n][1]);
                            const float p10 = ex2(SC[rc][n][2]);
                            const float p11 = ex2(SC[rc][n][3]);
                            Ph[rc][n * 2]     = cvt_f16x2(p01, p00);
                            Ph[rc][n * 2 + 1] = cvt_f16x2(p11, p10);
                        }
                } else {
                    #pragma unroll
                    for (int rc = 0; rc < 2; rc++) {
                        const int qr0 = qbase + rg * 32 + rc * 16 + l4;
                        const int qr1 = qr0 + 8;
                        #pragma unroll
                        for (int n = 0; n < 2; n++) {
                            const int key = kt + kb0 + kp * 16 + n * 8 + 2 * lq;
                            const float p00 = (key     <= qr0) ? ex2(SC[rc][n][0]) : 0.f;
                            const float p01 = (key + 1 <= qr0) ? ex2(SC[rc][n][1]) : 0.f;
                            const float p10 = (key     <= qr1) ? ex2(SC[rc][n][2]) : 0.f;
                            const float p11 = (key + 1 <= qr1) ? ex2(SC[rc][n][3]) : 0.f;
                            Ph[rc][n * 2]     = cvt_f16x2(p01, p00);
                            Ph[rc][n * 2 + 1] = cvt_f16x2(p11, p10);
                        }
                    }
                }

                // ---- l += P . mask ----
                {
                    const uint32_t a = padb + (uint32_t)(kb0 + kp * 16 + 2 * lq) * 2;
                    uint32_t bm[2];
                    bm[0] = lds32(a);
                    bm[1] = lds32(a + 16);
                    #pragma unroll
                    for (int rc = 0; rc < 2; rc++) mma_f16(LM[rc], Ph[rc], bm);
                }

                // ---- O += P V ----
                {
                    const int vrow = kb0 + kp * 16 + (g8 & 1) * 8 + l8;
                    #pragma unroll
                    for (int ndp = 0; ndp < 4; ndp++) {
                        const int c = 2 * ndp + (g8 >> 1);
                        uint32_t bh[4];
                        ldm_x4_t(bh, stb + OFF_V + vrow * 128 + (((uint32_t)(c ^ (vrow & 7))) << 4));
                        #pragma unroll
                        for (int rc = 0; rc < 2; rc++) {
                            mma_f16(OC[rc][2*ndp],   Ph[rc], bh);
                            mma_f16(OC[rc][2*ndp+1], Ph[rc], bh + 2);
                        }
                    }
                }
            }

            if (j + 1 < nkt) CP_WAIT0();
            __syncthreads();
        }

        // ---- merge the four key-quarters (ADD; no rescaling needed) ----
        if (lq == 0) {
            #pragma unroll
            for (int rc = 0; rc < 2; rc++) {
                lsm[wc * 64 + rg * 32 + rc * 16 + l4]     = LM[rc][0];
                lsm[wc * 64 + rg * 32 + rc * 16 + 8 + l4] = LM[rc][2];
            }
        }
        if (wc != 0) {
            float* mq = mrg + (wc - 1) * 4096;
            #pragma unroll
            for (int rc = 0; rc < 2; rc++) {
                const int r0 = rg * 32 + rc * 16 + l4;
                #pragma unroll
                for (int nd = 0; nd < 8; nd++) {
                    const int d0 = nd * 8 + 2 * lq;
                    *reinterpret_cast<float2*>(&mq[r0 * 64 + d0]) =
                        make_float2(OC[rc][nd][0], OC[rc][nd][1]);
                    *reinterpret_cast<float2*>(&mq[(r0 + 8) * 64 + d0]) =
                        make_float2(OC[rc][nd][2], OC[rc][nd][3]);
                }
            }
        }
        __syncthreads();
        if (wc == 0) {
            #pragma unroll
            for (int rc = 0; rc < 2; rc++) {
                const int r0 = rg * 32 + rc * 16 + l4;
                const float lt0 = lsm[r0] + lsm[64 + r0] + lsm[128 + r0] + lsm[192 + r0];
                const float lt1 = lsm[r0 + 8] + lsm[64 + r0 + 8] + lsm[128 + r0 + 8] + lsm[192 + r0 + 8];
                const bool am0 = (lt0 == 0.f), am1 = (lt1 == 0.f);
                const float inv0 = am0 ? 0.f : 1.f / lt0;
                const float inv1 = am1 ? 0.f : 1.f / lt1;
                const int qr0 = qbase + r0, qr1 = qr0 + 8;
                #pragma unroll
                for (int nd = 0; nd < 8; nd++) {
                    const int d0 = nd * 8 + 2 * lq;
                    float a0 = OC[rc][nd][0], a1 = OC[rc][nd][1];
                    float a2 = OC[rc][nd][2], a3 = OC[rc][nd][3];
                    #pragma unroll
                    for (int qq = 0; qq < 3; qq++) {
                        const float* mq = mrg + qq * 4096;
                        const float2 m0v = *reinterpret_cast<const float2*>(&mq[r0 * 64 + d0]);
                        const float2 m1v = *reinterpret_cast<const float2*>(&mq[(r0 + 8) * 64 + d0]);
                        a0 += m0v.x; a1 += m0v.y; a2 += m1v.x; a3 += m1v.y;
                    }
                    float2 o0, o1;
                    if (am0) o0 = make_float2(mnv[d0], mnv[d0 + 1]);
                    else     o0 = make_float2(a0 * inv0, a1 * inv0);
                    if (am1) o1 = make_float2(mnv[d0], mnv[d0 + 1]);
                    else     o1 = make_float2(a2 * inv1, a3 * inv1);
                    *reinterpret_cast<float2*>(&out[((size_t)b * S_ + qr0) * D_ + d0]) = o0;
                    *reinterpret_cast<float2*>(&out[((size_t)b * S_ + qr1) * D_ + d0]) = o1;
                }
            }
        }
    }
}

// ---------------------------------------------------------------------------
extern "C" void kernel_launch(void* const* d_in, const int* in_sizes, int n_in,
                              void* d_out, int out_size)
{
    const float* E  = (const float*)d_in[0];
    const float* PK = (const float*)d_in[1];
    const float* PV = (const float*)d_in[2];
    const float* Wq = (const float*)d_in[3];
    const float* bq = (const float*)d_in[4];
    const float* Wk = (const float*)d_in[5];
    const float* bk = (const float*)d_in[6];
    const float* Wv = (const float*)d_in[7];
    const float* bv = (const float*)d_in[8];
    const void*  pad = d_in[9];
    float* out = (float*)d_out;

    cudaFuncSetAttribute(proj_kernel, cudaFuncAttributeMaxDynamicSharedMemorySize, PROJ_SMEM);
    cudaFuncSetAttribute(attn_mma_kernel, cudaFuncAttributeMaxDynamicSharedMemorySize, SM_TOTAL);

    proj_kernel<<<128, 256, PROJ_SMEM>>>(E, PK, PV, Wq, bq, Wk, bk, Wv, bv, pad);
    attn_mma_kernel<<<dim3(32, B_), 256, SM_TOTAL>>>(out);
}